// round 14
// baseline (speedup 1.0000x reference)
#include <cuda_runtime.h>
#include <cuda_fp16.h>
#include <cstdint>

#define BATCH 4
#define SEQ   4096
#define DIM   256
#define RSB   528

// Attention operands: plain fp16, row-major
static __device__ __align__(16) __half g_Q[(size_t)BATCH * SEQ * DIM];
static __device__ __align__(16) __half g_K[(size_t)BATCH * SEQ * DIM];
static __device__ __align__(16) __half g_V[(size_t)BATCH * SEQ * DIM];
// Projection weights, fp16
static __device__ __align__(16) __half g_W16[3 * DIM * DIM];

// ---------------------------------------------------------------------------
__device__ __forceinline__ uint32_t smem_to_u32(const void* p) {
    uint32_t a;
    asm("{ .reg .u64 t; cvta.to.shared.u64 t, %1; cvt.u32.u64 %0, t; }"
        : "=r"(a) : "l"(p));
    return a;
}
__device__ __forceinline__ void mma_f16(float* d, const uint32_t* a, const uint32_t* b) {
    asm volatile(
        "mma.sync.aligned.m16n8k16.row.col.f32.f16.f16.f32 "
        "{%0,%1,%2,%3}, {%4,%5,%6,%7}, {%8,%9}, {%0,%1,%2,%3};"
        : "+f"(d[0]), "+f"(d[1]), "+f"(d[2]), "+f"(d[3])
        : "r"(a[0]), "r"(a[1]), "r"(a[2]), "r"(a[3]), "r"(b[0]), "r"(b[1]));
}
__device__ __forceinline__ void ldsm_x4(uint32_t* r, uint32_t addr) {
    asm volatile("ldmatrix.sync.aligned.m8n8.x4.shared.b16 {%0,%1,%2,%3}, [%4];"
        : "=r"(r[0]), "=r"(r[1]), "=r"(r[2]), "=r"(r[3]) : "r"(addr));
}
__device__ __forceinline__ void ldsm_x4_t(uint32_t* r, uint32_t addr) {
    asm volatile("ldmatrix.sync.aligned.m8n8.x4.trans.shared.b16 {%0,%1,%2,%3}, [%4];"
        : "=r"(r[0]), "=r"(r[1]), "=r"(r[2]), "=r"(r[3]) : "r"(addr));
}
__device__ __forceinline__ void cp16(uint32_t dst, const void* src) {
    asm volatile("cp.async.cg.shared.global [%0], [%1], 16;" :: "r"(dst), "l"(src));
}
#define CP_COMMIT() asm volatile("cp.async.commit_group;" ::: "memory")
#define CP_WAIT(n)  asm volatile("cp.async.wait_group %0;" :: "n"(n) : "memory")

__device__ __forceinline__ float ex2f(float x) {
    float y;
    asm("ex2.approx.ftz.f32 %0, %1;" : "=f"(y) : "f"(x));
    return y;
}
__device__ __forceinline__ uint32_t cvt_h2(float lo, float hi) {
    uint32_t r;
    asm("cvt.rn.f16x2.f32 %0, %1, %2;" : "=r"(r) : "f"(hi), "f"(lo));
    return r;
}

// ---------------------------------------------------------------------------
// W convert: fp32 -> fp16
// ---------------------------------------------------------------------------
__global__ __launch_bounds__(256) void conv_w_kernel(
    const float* __restrict__ Wq, const float* __restrict__ Wk,
    const float* __restrict__ Wv)
{
    const int wsel = blockIdx.y;
    const float* W = (wsel == 0) ? Wq : (wsel == 1) ? Wk : Wv;
    int idx = (blockIdx.x * 256 + threadIdx.x) * 4;
    float4 v = *(const float4*)&W[idx];
    size_t base = (size_t)wsel * DIM * DIM + idx;
    *(uint2*)&g_W16[base] = make_uint2(cvt_h2(v.x, v.y), cvt_h2(v.z, v.w));
}

// ---------------------------------------------------------------------------
// Single-pass fp16 projections. 128-row W chunks (6 chunks, 12 syncs).
// SMEM: x 67584 + 2 * 67584 = 202752 bytes.
// ---------------------------------------------------------------------------
#define PX_OFF  0
#define PW_OFF  (128 * RSB)
#define PWBUF   (128 * RSB)
#define PROJ_SMEM (PW_OFF + 2 * PWBUF)   // 202752

__global__ __launch_bounds__(256, 1) void proj_mma(
    const float* __restrict__ x,
    const float* __restrict__ bq, const float* __restrict__ bk,
    const float* __restrict__ bv)
{
    extern __shared__ char smem[];
    const uint32_t sb = smem_to_u32(smem);
    const int tid = threadIdx.x;
    const int lane = tid & 31;
    const int w = tid >> 5;
    const int m0 = blockIdx.x * 128;

    const uint32_t sX = sb + PX_OFF;
    uint32_t sW[2] = {sb + PW_OFF, sb + PW_OFF + PWBUF};

    // prefetch W chunk 0 (Wq rows 0..127): 4096 16B lines
#pragma unroll
    for (int i = 0; i < 16; i++) {
        int idx = tid + i * 256;
        int row = idx >> 5, c16 = idx & 31;
        uint32_t d = (uint32_t)row * RSB + c16 * 16;
        cp16(sW[0] + d, g_W16 + (size_t)row * DIM + c16 * 8);
    }
    CP_COMMIT();

    // load + convert resident x tile
#pragma unroll
    for (int i = 0; i < 32; i++) {
        int idx = tid + i * 256;
        int row = idx >> 6, c4 = idx & 63;
        float4 v = *(const float4*)&x[(size_t)(m0 + row) * DIM + c4 * 4];
        uint32_t d = (uint32_t)row * RSB + c4 * 8;
        *(uint2*)(smem + PX_OFF + d) = make_uint2(cvt_h2(v.x, v.y), cvt_h2(v.z, v.w));
    }

    const uint32_t aoff = (uint32_t)(16 * w + (lane & 15)) * RSB + ((lane & 16) ? 16u : 0u);
    const uint32_t boff = (uint32_t)((lane & 7) + ((lane & 8) ? 8 : 0)) * RSB + ((lane & 16) ? 16u : 0u);

    float oacc[32][4];
#pragma unroll
    for (int i = 0; i < 32; i++)
#pragma unroll
        for (int j = 0; j < 4; j++) oacc[i][j] = 0.f;

#pragma unroll 1
    for (int c = 0; c < 6; c++) {
        const int buf = c & 1;
        if (c < 5) {
            const int wsel = (c + 1) >> 1;
            const int k0 = ((c + 1) & 1) * 128;
            const size_t gbase = (size_t)wsel * DIM * DIM + (size_t)k0 * DIM;
#pragma unroll
            for (int i = 0; i < 16; i++) {
                int idx = tid + i * 256;
                int row = idx >> 5, c16 = idx & 31;
                uint32_t d = (uint32_t)row * RSB + c16 * 16;
                cp16(sW[buf ^ 1] + d, g_W16 + gbase + (size_t)row * DIM + c16 * 8);
            }
            CP_COMMIT();
            CP_WAIT(1);
        } else {
            CP_WAIT(0);
        }
        __syncthreads();

        const int kbase = (c & 1) * 128;
#pragma unroll
        for (int ks = 0; ks < 8; ks++) {
            uint32_t af[4];
            ldsm_x4(af, sX + aoff + (uint32_t)(kbase + ks * 16) * 2);
#pragma unroll
            for (int nt = 0; nt < 16; nt++) {
                uint32_t bf[4];
                uint32_t a = (uint32_t)ks * 16 * RSB + boff + (uint32_t)nt * 32;
                ldsm_x4_t(bf, sW[buf] + a);
#pragma unroll
                for (int h = 0; h < 2; h++)
                    mma_f16(oacc[nt * 2 + h], af, &bf[2 * h]);
            }
        }

        if ((c & 1) == 1) {
            const int wsel = c >> 1;
            const float* bias = (wsel == 0) ? bq : (wsel == 1) ? bk : bv;
            __half* dst = (wsel == 0) ? g_Q : (wsel == 1) ? g_K : g_V;
            const int r0 = m0 + 16 * w + (lane >> 2);
            const size_t base0 = (size_t)r0 * DIM + (lane & 3) * 2;
            const size_t base1 = base0 + (size_t)8 * DIM;
#pragma unroll
            for (int nto = 0; nto < 32; nto++) {
                const int col = nto * 8 + (lane & 3) * 2;
                float b0 = bias[col], b1 = bias[col + 1];
                *(uint32_t*)&dst[base0 + nto * 8] =
                    cvt_h2(oacc[nto][0] + b0, oacc[nto][1] + b1);
                *(uint32_t*)&dst[base1 + nto * 8] =
                    cvt_h2(oacc[nto][2] + b0, oacc[nto][3] + b1);
                oacc[nto][0] = oacc[nto][1] = oacc[nto][2] = oacc[nto][3] = 0.f;
            }
        }
        __syncthreads();
    }
}

// ---------------------------------------------------------------------------
// Attention: fp16 mma, pipelined (softmax(t); PV(t) || S(t+1)),
// Q register-resident, triple-buffered {K,V}, 3x-unrolled constant buffers.
// ---------------------------------------------------------------------------
#define AQ_OFF   0
#define ABUF_OFF (128 * RSB)
#define ABUF_STR (2 * 32 * RSB)
#define ATTN_SMEM (ABUF_OFF + 3 * ABUF_STR)  // 168960
#define NKT 128

__global__ __launch_bounds__(256, 1) void attn_mma(float* __restrict__ out)
{
    extern __shared__ char smem[];
    const uint32_t sb = smem_to_u32(smem);
    const int tid = threadIdx.x;
    const int lane = tid & 31;
    const int w = tid >> 5;
    const int b = blockIdx.y;
    const int q0 = blockIdx.x * 128;

    const uint32_t sQ = sb + AQ_OFF;
    const size_t kvbase = (size_t)b * SEQ * DIM;

#define ISSUE_TILE(tile, bs) do {                                          \
    const size_t _g = kvbase + (size_t)(tile) * 32 * DIM;                  \
    const uint32_t _bb = sb + ABUF_OFF + (uint32_t)(bs) * ABUF_STR;        \
    _Pragma("unroll")                                                      \
    for (int _i = 0; _i < 4; _i++) {                                       \
        int _idx = tid + _i * 256;                                         \
        int _row = _idx >> 5, _ch = _idx & 31;                             \
        uint32_t _d = (uint32_t)_row * RSB + _ch * 16;                     \
        size_t _go = _g + (size_t)_row * DIM + _ch * 8;                    \
        cp16(_bb + _d, g_K + _go);                                         \
        cp16(_bb + 32 * RSB + _d, g_V + _go);                              \
    }                                                                      \
} while (0)

    // prologue loads: Q + T0, then T1
    {
        const size_t qg = (size_t)(b * SEQ + q0) * DIM;
#pragma unroll
        for (int i = 0; i < 16; i++) {
            int idx = tid + i * 256;
            int row = idx >> 5, ch = idx & 31;
            uint32_t d = (uint32_t)row * RSB + ch * 16;
            cp16(sQ + d, g_Q + qg + (size_t)row * DIM + ch * 8);
        }
    }
    ISSUE_TILE(0, 0);
    CP_COMMIT();
    ISSUE_TILE(1, 1);
    CP_COMMIT();

    const uint32_t qoff = (uint32_t)(16 * w + (lane & 15)) * RSB + ((lane & 16) ? 16u : 0u);
    const uint32_t koff = (uint32_t)((lane & 7) + ((lane & 16) ? 8 : 0)) * RSB + ((lane & 8) ? 16u : 0u);
    const uint32_t voff = (uint32_t)((lane & 7) + ((lane & 8) ? 8 : 0)) * RSB + ((lane & 16) ? 16u : 0u);

    float oacc[32][4];
#pragma unroll
    for (int i = 0; i < 32; i++)
#pragma unroll
        for (int j = 0; j < 4; j++) oacc[i][j] = 0.f;
    float lsum0 = 0.f, lsum1 = 0.f;
    float sacc[4][4];
    uint32_t Pf[2][4];

    const float SC = 0.0625f * 1.4426950408889634f;

    // ---- prologue: Q -> registers, then S(0) ----
    CP_WAIT(1);
    __syncthreads();

    uint32_t qreg[16][4];
#pragma unroll
    for (int ks = 0; ks < 16; ks++)
        ldsm_x4(qreg[ks], sQ + qoff + ks * 32);

#pragma unroll
    for (int i = 0; i < 4; i++)
#pragma unroll
        for (int j = 0; j < 4; j++) sacc[i][j] = 0.f;
    {
        const uint32_t bK = sb + ABUF_OFF;   // buf 0
#pragma unroll 4
        for (int ks = 0; ks < 16; ks++) {
            uint32_t kf[2][4];
#pragma unroll
            for (int np = 0; np < 2; np++)
                ldsm_x4(kf[np], bK + koff + (uint32_t)np * 16 * RSB + ks * 32);
#pragma unroll
            for (int np = 0; np < 2; np++)
#pragma unroll
                for (int h = 0; h < 2; h++)
                    mma_f16(sacc[np * 2 + h], qreg[ks], &kf[np][2 * h]);
        }
    }

    // softmax(t): sacc -> Pf, zero sacc
#define SOFTMAX_STEP() do {                                                \
    _Pragma("unroll")                                                      \
    for (int nt = 0; nt < 4; nt++) {                                       \
        float p0 = ex2f(sacc[nt][0] * SC);                                 \
        float p1 = ex2f(sacc[nt][1] * SC);                                 \
        float p2 = ex2f(sacc[nt][2] * SC);                                 \
        float p3 = ex2f(sacc[nt][3] * SC);                                 \
        lsum0 += p0 + p1;                                                  \
        lsum1 += p2 + p3;                                                  \
        const int j = nt >> 1, bs = (nt & 1) * 2;                          \
        Pf[j][bs]     = cvt_h2(p0, p1);                                    \
        Pf[j][bs + 1] = cvt_h2(p2, p3);                                    \
    }                                                                      \
    _Pragma("unroll")                                                      \
    for (int _i = 0; _i < 4; _i++)                                         \
        _Pragma("unroll")                                                  \
        for (int _j = 0; _j < 4; _j++) sacc[_i][_j] = 0.f;                 \
} while (0)

    // one pipelined tile: wait, sync, issue(T+2,IB), softmax, PV(CB)||S(NB)
#define TILE_STEP(TG, CB, NB, IB, DO_ISSUE) do {                           \
    CP_WAIT(0);                                                            \
    __syncthreads();                                                       \
    if (DO_ISSUE) { ISSUE_TILE((TG) + 2, IB); CP_COMMIT(); }               \
    const uint32_t bV  = sb + ABUF_OFF + (uint32_t)(CB) * ABUF_STR + 32 * RSB; \
    const uint32_t bKn = sb + ABUF_OFF + (uint32_t)(NB) * ABUF_STR;        \
    SOFTMAX_STEP();                                                        \
    _Pragma("unroll")                                                      \
    for (int ks = 0; ks < 16; ks++) {                                      \
        uint32_t kf[2][4];                                                 \
        _Pragma("unroll")                                                  \
        for (int np = 0; np < 2; np++)                                     \
            ldsm_x4(kf[np], bKn + koff + (uint32_t)np * 16 * RSB + ks * 32); \
        _Pragma("unroll")                                                  \
        for (int np = 0; np < 2; np++)                                     \
            _Pragma("unroll")                                              \
            for (int h = 0; h < 2; h++)                                    \
                mma_f16(sacc[np * 2 + h], qreg[ks], &kf[np][2 * h]);       \
        _Pragma("unroll")                                                  \
        for (int u = 0; u < 2; u++) {                                      \
            const int i = ks * 2 + u;                                      \
            const int dblk = i >> 3, kc = (i >> 2) & 1, q = i & 3;         \
            uint32_t vf[4];                                                \
            ldsm_x4_t(vf, bV + (uint32_t)kc * 16 * RSB + voff +            \
                           (uint32_t)(dblk * 64 + q * 16) * 2);            \
            mma_f16(oacc[dblk * 8 + q * 2 + 0], Pf[kc], &vf[0]);           \
            mma_f16(oacc[dblk * 8 + q * 2 + 1], Pf[kc], &vf[2]);           \
        }                                                                  \
    }                                                                      \
} while (0)

    // tiles 0..125, 3x unrolled with constant buffer indices
#pragma unroll 1
    for (int t3 = 0; t3 < 42; t3++) {
        const int t = t3 * 3;
        { TILE_STEP(t + 0, 0, 1, 2, true); }
        { TILE_STEP(t + 1, 1, 2, 0, true); }
        { TILE_STEP(t + 2, 2, 0, 1, true); }
    }
    // tile 126: no further issue; S(127) still merged
    { TILE_STEP(126, 0, 1, 2, false); }
    // tile 127: softmax + PV only (buf 1)
    {
        const uint32_t bV = sb + ABUF_OFF + 1u * ABUF_STR + 32 * RSB;
        SOFTMAX_STEP();
#pragma unroll
        for (int i = 0; i < 32; i++) {
            const int dblk = i >> 3, kc = (i >> 2) & 1, q = i & 3;
            uint32_t vf[4];
            ldsm_x4_t(vf, bV + (uint32_t)kc * 16 * RSB + voff +
                           (uint32_t)(dblk * 64 + q * 16) * 2);
            mma_f16(oacc[dblk * 8 + q * 2 + 0], Pf[kc], &vf[0]);
            mma_f16(oacc[dblk * 8 + q * 2 + 1], Pf[kc], &vf[2]);
        }
    }

    // ---- epilogue ----
    lsum0 += __shfl_xor_sync(0xffffffffu, lsum0, 1);
    lsum0 += __shfl_xor_sync(0xffffffffu, lsum0, 2);
    lsum1 += __shfl_xor_sync(0xffffffffu, lsum1, 1);
    lsum1 += __shfl_xor_sync(0xffffffffu, lsum1, 2);
    const float inv0 = 1.0f / lsum0;
    const float inv1 = 1.0f / lsum1;

    const int r0 = q0 + 16 * w + (lane >> 2);
    const size_t base0 = ((size_t)b * SEQ + r0) * DIM + (lane & 3) * 2;
    const size_t base1 = base0 + (size_t)8 * DIM;
#pragma unroll
    for (int nto = 0; nto < 32; nto++) {
        float2 v0 = make_float2(oacc[nto][0] * inv0, oacc[nto][1] * inv0);
        float2 v1 = make_float2(oacc[nto][2] * inv1, oacc[nto][3] * inv1);
        *(float2*)&out[base0 + nto * 8] = v0;
        *(float2*)&out[base1 + nto * 8] = v1;
    }
}

// ---------------------------------------------------------------------------
extern "C" void kernel_launch(void* const* d_in, const int* in_sizes, int n_in,
                              void* d_out, int out_size)
{
    const float* x  = (const float*)d_in[0];
    const float* Wk = (const float*)d_in[1];
    const float* bk = (const float*)d_in[2];
    const float* Wq = (const float*)d_in[3];
    const float* bq = (const float*)d_in[4];
    const float* Wv = (const float*)d_in[5];
    const float* bv = (const float*)d_in[6];
    float* out = (float*)d_out;

    conv_w_kernel<<<dim3(64, 3), 256>>>(Wq, Wk, Wv);

    cudaFuncSetAttribute(proj_mma, cudaFuncAttributeMaxDynamicSharedMemorySize,
                         PROJ_SMEM);
    proj_mma<<<BATCH * SEQ / 128, 256, PROJ_SMEM>>>(x, bq, bk, bv);

    cudaFuncSetAttribute(attn_mma, cudaFuncAttributeMaxDynamicSharedMemorySize,
                         ATTN_SMEM);
    attn_mma<<<dim3(SEQ / 128, BATCH), 256, ATTN_SMEM>>>(out);
}

// round 15
// speedup vs baseline: 1.0693x; 1.0693x over previous
#include <cuda_runtime.h>
#include <cuda_fp16.h>
#include <cstdint>

#define BATCH 4
#define SEQ   4096
#define DIM   256
#define RSB   528

// Attention operands: plain fp16, row-major
static __device__ __align__(16) __half g_Q[(size_t)BATCH * SEQ * DIM];
static __device__ __align__(16) __half g_K[(size_t)BATCH * SEQ * DIM];
static __device__ __align__(16) __half g_V[(size_t)BATCH * SEQ * DIM];
// Projection weights, fp16
static __device__ __align__(16) __half g_W16[3 * DIM * DIM];

// ---------------------------------------------------------------------------
__device__ __forceinline__ uint32_t smem_to_u32(const void* p) {
    uint32_t a;
    asm("{ .reg .u64 t; cvta.to.shared.u64 t, %1; cvt.u32.u64 %0, t; }"
        : "=r"(a) : "l"(p));
    return a;
}
__device__ __forceinline__ void mma_f16(float* d, const uint32_t* a, const uint32_t* b) {
    asm volatile(
        "mma.sync.aligned.m16n8k16.row.col.f32.f16.f16.f32 "
        "{%0,%1,%2,%3}, {%4,%5,%6,%7}, {%8,%9}, {%0,%1,%2,%3};"
        : "+f"(d[0]), "+f"(d[1]), "+f"(d[2]), "+f"(d[3])
        : "r"(a[0]), "r"(a[1]), "r"(a[2]), "r"(a[3]), "r"(b[0]), "r"(b[1]));
}
__device__ __forceinline__ void ldsm_x4(uint32_t* r, uint32_t addr) {
    asm volatile("ldmatrix.sync.aligned.m8n8.x4.shared.b16 {%0,%1,%2,%3}, [%4];"
        : "=r"(r[0]), "=r"(r[1]), "=r"(r[2]), "=r"(r[3]) : "r"(addr));
}
__device__ __forceinline__ void ldsm_x4_t(uint32_t* r, uint32_t addr) {
    asm volatile("ldmatrix.sync.aligned.m8n8.x4.trans.shared.b16 {%0,%1,%2,%3}, [%4];"
        : "=r"(r[0]), "=r"(r[1]), "=r"(r[2]), "=r"(r[3]) : "r"(addr));
}
__device__ __forceinline__ void cp16(uint32_t dst, const void* src) {
    asm volatile("cp.async.cg.shared.global [%0], [%1], 16;" :: "r"(dst), "l"(src));
}
#define CP_COMMIT() asm volatile("cp.async.commit_group;" ::: "memory")
#define CP_WAIT(n)  asm volatile("cp.async.wait_group %0;" :: "n"(n) : "memory")

__device__ __forceinline__ float ex2f(float x) {
    float y;
    asm("ex2.approx.ftz.f32 %0, %1;" : "=f"(y) : "f"(x));
    return y;
}
__device__ __forceinline__ uint32_t cvt_h2(float lo, float hi) {
    uint32_t r;
    asm("cvt.rn.f16x2.f32 %0, %1, %2;" : "=r"(r) : "f"(hi), "f"(lo));
    return r;
}

// ---------------------------------------------------------------------------
// W convert: fp32 -> fp16
// ---------------------------------------------------------------------------
__global__ __launch_bounds__(256) void conv_w_kernel(
    const float* __restrict__ Wq, const float* __restrict__ Wk,
    const float* __restrict__ Wv)
{
    const int wsel = blockIdx.y;
    const float* W = (wsel == 0) ? Wq : (wsel == 1) ? Wk : Wv;
    int idx = (blockIdx.x * 256 + threadIdx.x) * 4;
    float4 v = *(const float4*)&W[idx];
    size_t base = (size_t)wsel * DIM * DIM + idx;
    *(uint2*)&g_W16[base] = make_uint2(cvt_h2(v.x, v.y), cvt_h2(v.z, v.w));
}

// ---------------------------------------------------------------------------
// Single-pass fp16 projections (exact R12 version, proven ~35us)
// ---------------------------------------------------------------------------
#define PX_OFF  0
#define PW_OFF  (128 * RSB)
#define PWBUF   (64 * RSB)
#define PROJ_SMEM (PW_OFF + 2 * PWBUF)

__global__ __launch_bounds__(256, 1) void proj_mma(
    const float* __restrict__ x,
    const float* __restrict__ bq, const float* __restrict__ bk,
    const float* __restrict__ bv)
{
    extern __shared__ char smem[];
    const uint32_t sb = smem_to_u32(smem);
    const int tid = threadIdx.x;
    const int lane = tid & 31;
    const int w = tid >> 5;
    const int m0 = blockIdx.x * 128;

    const uint32_t sX = sb + PX_OFF;
    uint32_t sW[2] = {sb + PW_OFF, sb + PW_OFF + PWBUF};

#pragma unroll
    for (int i = 0; i < 8; i++) {
        int idx = tid + i * 256;
        int row = idx >> 5, c16 = idx & 31;
        uint32_t d = (uint32_t)row * RSB + c16 * 16;
        cp16(sW[0] + d, g_W16 + (size_t)row * DIM + c16 * 8);
    }
    CP_COMMIT();

#pragma unroll
    for (int i = 0; i < 32; i++) {
        int idx = tid + i * 256;
        int row = idx >> 6, c4 = idx & 63;
        float4 v = *(const float4*)&x[(size_t)(m0 + row) * DIM + c4 * 4];
        uint32_t d = (uint32_t)row * RSB + c4 * 8;
        *(uint2*)(smem + PX_OFF + d) = make_uint2(cvt_h2(v.x, v.y), cvt_h2(v.z, v.w));
    }

    const uint32_t aoff = (uint32_t)(16 * w + (lane & 15)) * RSB + ((lane & 16) ? 16u : 0u);
    const uint32_t boff = (uint32_t)((lane & 7) + ((lane & 8) ? 8 : 0)) * RSB + ((lane & 16) ? 16u : 0u);

    float oacc[32][4];
#pragma unroll
    for (int i = 0; i < 32; i++)
#pragma unroll
        for (int j = 0; j < 4; j++) oacc[i][j] = 0.f;

#pragma unroll 1
    for (int c = 0; c < 12; c++) {
        const int buf = c & 1;
        if (c < 11) {
            const int wsel = (c + 1) >> 2;
            const int k0 = ((c + 1) & 3) * 64;
            const size_t gbase = (size_t)wsel * DIM * DIM + (size_t)k0 * DIM;
#pragma unroll
            for (int i = 0; i < 8; i++) {
                int idx = tid + i * 256;
                int row = idx >> 5, c16 = idx & 31;
                uint32_t d = (uint32_t)row * RSB + c16 * 16;
                cp16(sW[buf ^ 1] + d, g_W16 + gbase + (size_t)row * DIM + c16 * 8);
            }
            CP_COMMIT();
            CP_WAIT(1);
        } else {
            CP_WAIT(0);
        }
        __syncthreads();

        const int kbase = (c & 3) * 64;
#pragma unroll
        for (int ks = 0; ks < 4; ks++) {
            uint32_t af[4];
            ldsm_x4(af, sX + aoff + (uint32_t)(kbase + ks * 16) * 2);
#pragma unroll
            for (int nt = 0; nt < 16; nt++) {
                uint32_t bf[4];
                uint32_t a = (uint32_t)ks * 16 * RSB + boff + (uint32_t)nt * 32;
                ldsm_x4_t(bf, sW[buf] + a);
#pragma unroll
                for (int h = 0; h < 2; h++)
                    mma_f16(oacc[nt * 2 + h], af, &bf[2 * h]);
            }
        }

        if ((c & 3) == 3) {
            const int wsel = c >> 2;
            const float* bias = (wsel == 0) ? bq : (wsel == 1) ? bk : bv;
            __half* dst = (wsel == 0) ? g_Q : (wsel == 1) ? g_K : g_V;
            const int r0 = m0 + 16 * w + (lane >> 2);
            const size_t base0 = (size_t)r0 * DIM + (lane & 3) * 2;
            const size_t base1 = base0 + (size_t)8 * DIM;
#pragma unroll
            for (int nto = 0; nto < 32; nto++) {
                const int col = nto * 8 + (lane & 3) * 2;
                float b0 = bias[col], b1 = bias[col + 1];
                *(uint32_t*)&dst[base0 + nto * 8] =
                    cvt_h2(oacc[nto][0] + b0, oacc[nto][1] + b1);
                *(uint32_t*)&dst[base1 + nto * 8] =
                    cvt_h2(oacc[nto][2] + b0, oacc[nto][3] + b1);
                oacc[nto][0] = oacc[nto][1] = oacc[nto][2] = oacc[nto][3] = 0.f;
            }
        }
        __syncthreads();
    }
}

// ---------------------------------------------------------------------------
// Attention: R12 structure (pipelined softmax(t); PV(t) || S(t+1), Q in regs,
// triple-buffered {K,V}, rolled loop) + distance-1 K-fragment prefetch.
// ---------------------------------------------------------------------------
#define AQ_OFF   0
#define ABUF_OFF (128 * RSB)
#define ABUF_STR (2 * 32 * RSB)
#define ATTN_SMEM (ABUF_OFF + 3 * ABUF_STR)  // 168960
#define NKT 128

__global__ __launch_bounds__(256, 1) void attn_mma(float* __restrict__ out)
{
    extern __shared__ char smem[];
    const uint32_t sb = smem_to_u32(smem);
    const int tid = threadIdx.x;
    const int lane = tid & 31;
    const int w = tid >> 5;
    const int b = blockIdx.y;
    const int q0 = blockIdx.x * 128;

    const uint32_t sQ = sb + AQ_OFF;
    const size_t kvbase = (size_t)b * SEQ * DIM;

#define ISSUE_TILE(tile, bs) do {                                          \
    const size_t _g = kvbase + (size_t)(tile) * 32 * DIM;                  \
    const uint32_t _bb = sb + ABUF_OFF + (uint32_t)(bs) * ABUF_STR;        \
    _Pragma("unroll")                                                      \
    for (int _i = 0; _i < 4; _i++) {                                       \
        int _idx = tid + _i * 256;                                         \
        int _row = _idx >> 5, _ch = _idx & 31;                             \
        uint32_t _d = (uint32_t)_row * RSB + _ch * 16;                     \
        size_t _go = _g + (size_t)_row * DIM + _ch * 8;                    \
        cp16(_bb + _d, g_K + _go);                                         \
        cp16(_bb + 32 * RSB + _d, g_V + _go);                              \
    }                                                                      \
} while (0)

    // prologue loads: Q + T0, then T1
    {
        const size_t qg = (size_t)(b * SEQ + q0) * DIM;
#pragma unroll
        for (int i = 0; i < 16; i++) {
            int idx = tid + i * 256;
            int row = idx >> 5, ch = idx & 31;
            uint32_t d = (uint32_t)row * RSB + ch * 16;
            cp16(sQ + d, g_Q + qg + (size_t)row * DIM + ch * 8);
        }
    }
    ISSUE_TILE(0, 0);
    CP_COMMIT();
    ISSUE_TILE(1, 1);
    CP_COMMIT();

    const uint32_t qoff = (uint32_t)(16 * w + (lane & 15)) * RSB + ((lane & 16) ? 16u : 0u);
    const uint32_t koff = (uint32_t)((lane & 7) + ((lane & 16) ? 8 : 0)) * RSB + ((lane & 8) ? 16u : 0u);
    const uint32_t voff = (uint32_t)((lane & 7) + ((lane & 8) ? 8 : 0)) * RSB + ((lane & 16) ? 16u : 0u);

    float oacc[32][4];
#pragma unroll
    for (int i = 0; i < 32; i++)
#pragma unroll
        for (int j = 0; j < 4; j++) oacc[i][j] = 0.f;
    float lsum0 = 0.f, lsum1 = 0.f;
    float sacc[4][4];
    uint32_t Pf[2][4];

    const float SC = 0.0625f * 1.4426950408889634f;

    // ---- prologue: Q -> registers (once), then S(0) ----
    CP_WAIT(1);
    __syncthreads();

    uint32_t qreg[16][4];
#pragma unroll
    for (int ks = 0; ks < 16; ks++)
        ldsm_x4(qreg[ks], sQ + qoff + ks * 32);

#pragma unroll
    for (int i = 0; i < 4; i++)
#pragma unroll
        for (int j = 0; j < 4; j++) sacc[i][j] = 0.f;
    {
        const uint32_t bK = sb + ABUF_OFF;   // buf 0
#pragma unroll 4
        for (int ks = 0; ks < 16; ks++) {
            uint32_t kf[2][4];
#pragma unroll
            for (int np = 0; np < 2; np++)
                ldsm_x4(kf[np], bK + koff + (uint32_t)np * 16 * RSB + ks * 32);
#pragma unroll
            for (int np = 0; np < 2; np++)
#pragma unroll
                for (int h = 0; h < 2; h++)
                    mma_f16(sacc[np * 2 + h], qreg[ks], &kf[np][2 * h]);
        }
    }

    // K-fragment load into a named buffer
#define LOADK(dst, bKn, ks) do {                                           \
    ldsm_x4((dst)[0], (bKn) + koff + (uint32_t)(ks) * 32);                 \
    ldsm_x4((dst)[1], (bKn) + koff + 16u * RSB + (uint32_t)(ks) * 32);     \
} while (0)
    // 4 S-mma for one kstep from a named buffer
#define SMMA(src, ks) do {                                                 \
    mma_f16(sacc[0], qreg[ks], &(src)[0][0]);                              \
    mma_f16(sacc[1], qreg[ks], &(src)[0][2]);                              \
    mma_f16(sacc[2], qreg[ks], &(src)[1][0]);                              \
    mma_f16(sacc[3], qreg[ks], &(src)[1][2]);                              \
} while (0)
    // PV work paired with kstep ks (indices i = ks*2, ks*2+1)
#define PVSTEP(bV, ks) do {                                                \
    _Pragma("unroll")                                                      \
    for (int _u = 0; _u < 2; _u++) {                                       \
        const int _i = (ks) * 2 + _u;                                      \
        const int _dblk = _i >> 3, _kc = (_i >> 2) & 1, _q = _i & 3;       \
        uint32_t _vf[4];                                                   \
        ldsm_x4_t(_vf, (bV) + (uint32_t)_kc * 16 * RSB + voff +            \
                       (uint32_t)(_dblk * 64 + _q * 16) * 2);              \
        mma_f16(oacc[_dblk * 8 + _q * 2 + 0], Pf[_kc], &_vf[0]);           \
        mma_f16(oacc[_dblk * 8 + _q * 2 + 1], Pf[_kc], &_vf[2]);           \
    }                                                                      \
} while (0)

    int cb = 0, ib = 2;   // cb = buf(t), ib = buf(t+2)

#pragma unroll 1
    for (int t = 0; t < NKT; t++) {
        CP_WAIT(0);
        __syncthreads();
        if (t + 2 < NKT) { ISSUE_TILE(t + 2, ib); CP_COMMIT(); }

        const int nb = (cb == 2) ? 0 : cb + 1;            // buf(t+1)
        const uint32_t bV  = sb + ABUF_OFF + (uint32_t)cb * ABUF_STR + 32 * RSB;
        const uint32_t bKn = sb + ABUF_OFF + (uint32_t)nb * ABUF_STR;

        // ---- softmax(t): sacc -> Pf ----
#pragma unroll
        for (int nt = 0; nt < 4; nt++) {
            float p0 = ex2f(sacc[nt][0] * SC);
            float p1 = ex2f(sacc[nt][1] * SC);
            float p2 = ex2f(sacc[nt][2] * SC);
            float p3 = ex2f(sacc[nt][3] * SC);
            lsum0 += p0 + p1;
            lsum1 += p2 + p3;
            const int j = nt >> 1, bs = (nt & 1) * 2;
            Pf[j][bs]     = cvt_h2(p0, p1);
            Pf[j][bs + 1] = cvt_h2(p2, p3);
        }
#pragma unroll
        for (int i = 0; i < 4; i++)
#pragma unroll
            for (int j = 0; j < 4; j++) sacc[i][j] = 0.f;

        // ---- merged: PV(t) || S(t+1), K fragments prefetched 1 kstep ahead ----
        if (t + 1 < NKT) {
            uint32_t kf0[2][4], kf1[2][4];
            LOADK(kf0, bKn, 0);
#pragma unroll
            for (int ks2 = 0; ks2 < 8; ks2++) {
                const int kse = ks2 * 2;          // even kstep: consume kf0
                if (kse + 1 < 16) LOADK(kf1, bKn, kse + 1);
                SMMA(kf0, kse);
                PVSTEP(bV, kse);
                const int kso = kse + 1;          // odd kstep: consume kf1
                if (kso + 1 < 16) LOADK(kf0, bKn, kso + 1);
                SMMA(kf1, kso);
                PVSTEP(bV, kso);
            }
        } else {
#pragma unroll
            for (int ks = 0; ks < 16; ks++)
                PVSTEP(bV, ks);
        }

        cb = (cb == 2) ? 0 : cb + 1;
        ib = (ib == 2) ? 0 : ib + 1;
    }

    // ---- epilogue ----
    lsum0 += __shfl_xor_sync(0xffffffffu, lsum0, 1);
    lsum0 += __shfl_xor_sync(0xffffffffu, lsum0, 2);
    lsum1 += __shfl_xor_sync(0xffffffffu, lsum1, 1);
    lsum1 += __shfl_xor_sync(0xffffffffu, lsum1, 2);
    const float inv0 = 1.0f / lsum0;
    const float inv1 = 1.0f / lsum1;

    const int r0 = q0 + 16 * w + (lane >> 2);
    const size_t base0 = ((size_t)b * SEQ + r0) * DIM + (lane & 3) * 2;
    const size_t base1 = base0 + (size_t)8 * DIM;
#pragma unroll
    for (int nto = 0; nto < 32; nto++) {
        float2 v0 = make_float2(oacc[nto][0] * inv0, oacc[nto][1] * inv0);
        float2 v1 = make_float2(oacc[nto][2] * inv1, oacc[nto][3] * inv1);
        *(float2*)&out[base0 + nto * 8] = v0;
        *(float2*)&out[base1 + nto * 8] = v1;
    }
}

// ---------------------------------------------------------------------------
extern "C" void kernel_launch(void* const* d_in, const int* in_sizes, int n_in,
                              void* d_out, int out_size)
{
    const float* x  = (const float*)d_in[0];
    const float* Wk = (const float*)d_in[1];
    const float* bk = (const float*)d_in[2];
    const float* Wq = (const float*)d_in[3];
    const float* bq = (const float*)d_in[4];
    const float* Wv = (const float*)d_in[5];
    const float* bv = (const float*)d_in[6];
    float* out = (float*)d_out;

    conv_w_kernel<<<dim3(64, 3), 256>>>(Wq, Wk, Wv);

    cudaFuncSetAttribute(proj_mma, cudaFuncAttributeMaxDynamicSharedMemorySize,
                         PROJ_SMEM);
    proj_mma<<<BATCH * SEQ / 128, 256, PROJ_SMEM>>>(x, bq, bk, bv);

    cudaFuncSetAttribute(attn_mma, cudaFuncAttributeMaxDynamicSharedMemorySize,
                         ATTN_SMEM);
    attn_mma<<<dim3(SEQ / 128, BATCH), 256, ATTN_SMEM>>>(out);
}

// round 16
// speedup vs baseline: 1.0755x; 1.0058x over previous
#include <cuda_runtime.h>
#include <cuda_fp16.h>
#include <cstdint>

#define BATCH 4
#define SEQ   4096
#define DIM   256
#define RSB   528

// Attention operands: plain fp16, row-major
static __device__ __align__(16) __half g_Q[(size_t)BATCH * SEQ * DIM];
static __device__ __align__(16) __half g_K[(size_t)BATCH * SEQ * DIM];
static __device__ __align__(16) __half g_V[(size_t)BATCH * SEQ * DIM];
// Projection weights, fp16
static __device__ __align__(16) __half g_W16[3 * DIM * DIM];

// ---------------------------------------------------------------------------
__device__ __forceinline__ uint32_t smem_to_u32(const void* p) {
    uint32_t a;
    asm("{ .reg .u64 t; cvta.to.shared.u64 t, %1; cvt.u32.u64 %0, t; }"
        : "=r"(a) : "l"(p));
    return a;
}
__device__ __forceinline__ void mma_f16(float* d, const uint32_t* a, const uint32_t* b) {
    asm volatile(
        "mma.sync.aligned.m16n8k16.row.col.f32.f16.f16.f32 "
        "{%0,%1,%2,%3}, {%4,%5,%6,%7}, {%8,%9}, {%0,%1,%2,%3};"
        : "+f"(d[0]), "+f"(d[1]), "+f"(d[2]), "+f"(d[3])
        : "r"(a[0]), "r"(a[1]), "r"(a[2]), "r"(a[3]), "r"(b[0]), "r"(b[1]));
}
__device__ __forceinline__ void ldsm_x4(uint32_t* r, uint32_t addr) {
    asm volatile("ldmatrix.sync.aligned.m8n8.x4.shared.b16 {%0,%1,%2,%3}, [%4];"
        : "=r"(r[0]), "=r"(r[1]), "=r"(r[2]), "=r"(r[3]) : "r"(addr));
}
__device__ __forceinline__ void ldsm_x4_t(uint32_t* r, uint32_t addr) {
    asm volatile("ldmatrix.sync.aligned.m8n8.x4.trans.shared.b16 {%0,%1,%2,%3}, [%4];"
        : "=r"(r[0]), "=r"(r[1]), "=r"(r[2]), "=r"(r[3]) : "r"(addr));
}
__device__ __forceinline__ void cp16(uint32_t dst, const void* src) {
    asm volatile("cp.async.cg.shared.global [%0], [%1], 16;" :: "r"(dst), "l"(src));
}
#define CP_COMMIT() asm volatile("cp.async.commit_group;" ::: "memory")
#define CP_WAIT(n)  asm volatile("cp.async.wait_group %0;" :: "n"(n) : "memory")

__device__ __forceinline__ float ex2f(float x) {
    float y;
    asm("ex2.approx.ftz.f32 %0, %1;" : "=f"(y) : "f"(x));
    return y;
}
__device__ __forceinline__ uint32_t cvt_h2(float lo, float hi) {
    uint32_t r;
    asm("cvt.rn.f16x2.f32 %0, %1, %2;" : "=r"(r) : "f"(hi), "f"(lo));
    return r;
}

// ---------------------------------------------------------------------------
// W convert: fp32 -> fp16
// ---------------------------------------------------------------------------
__global__ __launch_bounds__(256) void conv_w_kernel(
    const float* __restrict__ Wq, const float* __restrict__ Wk,
    const float* __restrict__ Wv)
{
    const int wsel = blockIdx.y;
    const float* W = (wsel == 0) ? Wq : (wsel == 1) ? Wk : Wv;
    int idx = (blockIdx.x * 256 + threadIdx.x) * 4;
    float4 v = *(const float4*)&W[idx];
    size_t base = (size_t)wsel * DIM * DIM + idx;
    *(uint2*)&g_W16[base] = make_uint2(cvt_h2(v.x, v.y), cvt_h2(v.z, v.w));
}

// ---------------------------------------------------------------------------
// Single-pass fp16 projections (exact R12 version, proven ~35us)
// ---------------------------------------------------------------------------
#define PX_OFF  0
#define PW_OFF  (128 * RSB)
#define PWBUF   (64 * RSB)
#define PROJ_SMEM (PW_OFF + 2 * PWBUF)

__global__ __launch_bounds__(256, 1) void proj_mma(
    const float* __restrict__ x,
    const float* __restrict__ bq, const float* __restrict__ bk,
    const float* __restrict__ bv)
{
    extern __shared__ char smem[];
    const uint32_t sb = smem_to_u32(smem);
    const int tid = threadIdx.x;
    const int lane = tid & 31;
    const int w = tid >> 5;
    const int m0 = blockIdx.x * 128;

    const uint32_t sX = sb + PX_OFF;
    uint32_t sW[2] = {sb + PW_OFF, sb + PW_OFF + PWBUF};

#pragma unroll
    for (int i = 0; i < 8; i++) {
        int idx = tid + i * 256;
        int row = idx >> 5, c16 = idx & 31;
        uint32_t d = (uint32_t)row * RSB + c16 * 16;
        cp16(sW[0] + d, g_W16 + (size_t)row * DIM + c16 * 8);
    }
    CP_COMMIT();

#pragma unroll
    for (int i = 0; i < 32; i++) {
        int idx = tid + i * 256;
        int row = idx >> 6, c4 = idx & 63;
        float4 v = *(const float4*)&x[(size_t)(m0 + row) * DIM + c4 * 4];
        uint32_t d = (uint32_t)row * RSB + c4 * 8;
        *(uint2*)(smem + PX_OFF + d) = make_uint2(cvt_h2(v.x, v.y), cvt_h2(v.z, v.w));
    }

    const uint32_t aoff = (uint32_t)(16 * w + (lane & 15)) * RSB + ((lane & 16) ? 16u : 0u);
    const uint32_t boff = (uint32_t)((lane & 7) + ((lane & 8) ? 8 : 0)) * RSB + ((lane & 16) ? 16u : 0u);

    float oacc[32][4];
#pragma unroll
    for (int i = 0; i < 32; i++)
#pragma unroll
        for (int j = 0; j < 4; j++) oacc[i][j] = 0.f;

#pragma unroll 1
    for (int c = 0; c < 12; c++) {
        const int buf = c & 1;
        if (c < 11) {
            const int wsel = (c + 1) >> 2;
            const int k0 = ((c + 1) & 3) * 64;
            const size_t gbase = (size_t)wsel * DIM * DIM + (size_t)k0 * DIM;
#pragma unroll
            for (int i = 0; i < 8; i++) {
                int idx = tid + i * 256;
                int row = idx >> 5, c16 = idx & 31;
                uint32_t d = (uint32_t)row * RSB + c16 * 16;
                cp16(sW[buf ^ 1] + d, g_W16 + gbase + (size_t)row * DIM + c16 * 8);
            }
            CP_COMMIT();
            CP_WAIT(1);
        } else {
            CP_WAIT(0);
        }
        __syncthreads();

        const int kbase = (c & 3) * 64;
#pragma unroll
        for (int ks = 0; ks < 4; ks++) {
            uint32_t af[4];
            ldsm_x4(af, sX + aoff + (uint32_t)(kbase + ks * 16) * 2);
#pragma unroll
            for (int nt = 0; nt < 16; nt++) {
                uint32_t bf[4];
                uint32_t a = (uint32_t)ks * 16 * RSB + boff + (uint32_t)nt * 32;
                ldsm_x4_t(bf, sW[buf] + a);
#pragma unroll
                for (int h = 0; h < 2; h++)
                    mma_f16(oacc[nt * 2 + h], af, &bf[2 * h]);
            }
        }

        if ((c & 3) == 3) {
            const int wsel = c >> 2;
            const float* bias = (wsel == 0) ? bq : (wsel == 1) ? bk : bv;
            __half* dst = (wsel == 0) ? g_Q : (wsel == 1) ? g_K : g_V;
            const int r0 = m0 + 16 * w + (lane >> 2);
            const size_t base0 = (size_t)r0 * DIM + (lane & 3) * 2;
            const size_t base1 = base0 + (size_t)8 * DIM;
#pragma unroll
            for (int nto = 0; nto < 32; nto++) {
                const int col = nto * 8 + (lane & 3) * 2;
                float b0 = bias[col], b1 = bias[col + 1];
                *(uint32_t*)&dst[base0 + nto * 8] =
                    cvt_h2(oacc[nto][0] + b0, oacc[nto][1] + b1);
                *(uint32_t*)&dst[base1 + nto * 8] =
                    cvt_h2(oacc[nto][2] + b0, oacc[nto][3] + b1);
                oacc[nto][0] = oacc[nto][1] = oacc[nto][2] = oacc[nto][3] = 0.f;
            }
        }
        __syncthreads();
    }
}

// ---------------------------------------------------------------------------
// Attention: R12 structure with softmax hoisted ABOVE the barrier.
// Loop body: softmax(t) [registers only] ; wait ; sync ; issue(t+2) ;
//            PV(t) || S(t+1).
// ---------------------------------------------------------------------------
#define AQ_OFF   0
#define ABUF_OFF (128 * RSB)
#define ABUF_STR (2 * 32 * RSB)
#define ATTN_SMEM (ABUF_OFF + 3 * ABUF_STR)  // 168960
#define NKT 128

__global__ __launch_bounds__(256, 1) void attn_mma(float* __restrict__ out)
{
    extern __shared__ char smem[];
    const uint32_t sb = smem_to_u32(smem);
    const int tid = threadIdx.x;
    const int lane = tid & 31;
    const int w = tid >> 5;
    const int b = blockIdx.y;
    const int q0 = blockIdx.x * 128;

    const uint32_t sQ = sb + AQ_OFF;
    const size_t kvbase = (size_t)b * SEQ * DIM;

#define ISSUE_TILE(tile, bs) do {                                          \
    const size_t _g = kvbase + (size_t)(tile) * 32 * DIM;                  \
    const uint32_t _bb = sb + ABUF_OFF + (uint32_t)(bs) * ABUF_STR;        \
    _Pragma("unroll")                                                      \
    for (int _i = 0; _i < 4; _i++) {                                       \
        int _idx = tid + _i * 256;                                         \
        int _row = _idx >> 5, _ch = _idx & 31;                             \
        uint32_t _d = (uint32_t)_row * RSB + _ch * 16;                     \
        size_t _go = _g + (size_t)_row * DIM + _ch * 8;                    \
        cp16(_bb + _d, g_K + _go);                                         \
        cp16(_bb + 32 * RSB + _d, g_V + _go);                              \
    }                                                                      \
} while (0)

    // prologue loads: Q + T0, then T1
    {
        const size_t qg = (size_t)(b * SEQ + q0) * DIM;
#pragma unroll
        for (int i = 0; i < 16; i++) {
            int idx = tid + i * 256;
            int row = idx >> 5, ch = idx & 31;
            uint32_t d = (uint32_t)row * RSB + ch * 16;
            cp16(sQ + d, g_Q + qg + (size_t)row * DIM + ch * 8);
        }
    }
    ISSUE_TILE(0, 0);
    CP_COMMIT();
    ISSUE_TILE(1, 1);
    CP_COMMIT();

    const uint32_t qoff = (uint32_t)(16 * w + (lane & 15)) * RSB + ((lane & 16) ? 16u : 0u);
    const uint32_t koff = (uint32_t)((lane & 7) + ((lane & 16) ? 8 : 0)) * RSB + ((lane & 8) ? 16u : 0u);
    const uint32_t voff = (uint32_t)((lane & 7) + ((lane & 8) ? 8 : 0)) * RSB + ((lane & 16) ? 16u : 0u);

    float oacc[32][4];
#pragma unroll
    for (int i = 0; i < 32; i++)
#pragma unroll
        for (int j = 0; j < 4; j++) oacc[i][j] = 0.f;
    float lsum0 = 0.f, lsum1 = 0.f;
    float sacc[4][4];
    uint32_t Pf[2][4];

    const float SC = 0.0625f * 1.4426950408889634f;

    // ---- prologue: Q -> registers (once), then S(0) ----
    CP_WAIT(1);
    __syncthreads();

    uint32_t qreg[16][4];
#pragma unroll
    for (int ks = 0; ks < 16; ks++)
        ldsm_x4(qreg[ks], sQ + qoff + ks * 32);

#pragma unroll
    for (int i = 0; i < 4; i++)
#pragma unroll
        for (int j = 0; j < 4; j++) sacc[i][j] = 0.f;
    {
        const uint32_t bK = sb + ABUF_OFF;   // buf 0
#pragma unroll 4
        for (int ks = 0; ks < 16; ks++) {
            uint32_t kf[2][4];
#pragma unroll
            for (int np = 0; np < 2; np++)
                ldsm_x4(kf[np], bK + koff + (uint32_t)np * 16 * RSB + ks * 32);
#pragma unroll
            for (int np = 0; np < 2; np++)
#pragma unroll
                for (int h = 0; h < 2; h++)
                    mma_f16(sacc[np * 2 + h], qreg[ks], &kf[np][2 * h]);
        }
    }

    int cb = 0, ib = 2;   // cb = buf(t), ib = buf(t+2)

#pragma unroll 1
    for (int t = 0; t < NKT; t++) {
        // ---- softmax(t): pure register work, hoisted ABOVE the barrier.
        // Overlaps the cp wait + syncthreads and de-correlates warp arrival.
#pragma unroll
        for (int nt = 0; nt < 4; nt++) {
            float p0 = ex2f(sacc[nt][0] * SC);
            float p1 = ex2f(sacc[nt][1] * SC);
            float p2 = ex2f(sacc[nt][2] * SC);
            float p3 = ex2f(sacc[nt][3] * SC);
            lsum0 += p0 + p1;
            lsum1 += p2 + p3;
            const int j = nt >> 1, bs = (nt & 1) * 2;
            Pf[j][bs]     = cvt_h2(p0, p1);
            Pf[j][bs + 1] = cvt_h2(p2, p3);
        }
#pragma unroll
        for (int i = 0; i < 4; i++)
#pragma unroll
            for (int j = 0; j < 4; j++) sacc[i][j] = 0.f;

        CP_WAIT(0);
        __syncthreads();
        if (t + 2 < NKT) { ISSUE_TILE(t + 2, ib); CP_COMMIT(); }

        const int nb = (cb == 2) ? 0 : cb + 1;            // buf(t+1)
        const uint32_t bV  = sb + ABUF_OFF + (uint32_t)cb * ABUF_STR + 32 * RSB;
        const uint32_t bKn = sb + ABUF_OFF + (uint32_t)nb * ABUF_STR;

        // ---- merged: PV(t) (32 q-iters) || S(t+1) (16 ksteps) ----
        if (t + 1 < NKT) {
#pragma unroll
            for (int ks = 0; ks < 16; ks++) {
                uint32_t kf[2][4];
#pragma unroll
                for (int np = 0; np < 2; np++)
                    ldsm_x4(kf[np], bKn + koff + (uint32_t)np * 16 * RSB + ks * 32);
#pragma unroll
                for (int np = 0; np < 2; np++)
#pragma unroll
                    for (int h = 0; h < 2; h++)
                        mma_f16(sacc[np * 2 + h], qreg[ks], &kf[np][2 * h]);
#pragma unroll
                for (int u = 0; u < 2; u++) {
                    const int i = ks * 2 + u;
                    const int dblk = i >> 3, kc = (i >> 2) & 1, q = i & 3;
                    uint32_t vf[4];
                    ldsm_x4_t(vf, bV + (uint32_t)kc * 16 * RSB + voff +
                                   (uint32_t)(dblk * 64 + q * 16) * 2);
                    mma_f16(oacc[dblk * 8 + q * 2 + 0], Pf[kc], &vf[0]);
                    mma_f16(oacc[dblk * 8 + q * 2 + 1], Pf[kc], &vf[2]);
                }
            }
        } else {
#pragma unroll
            for (int i = 0; i < 32; i++) {
                const int dblk = i >> 3, kc = (i >> 2) & 1, q = i & 3;
                uint32_t vf[4];
                ldsm_x4_t(vf, bV + (uint32_t)kc * 16 * RSB + voff +
                               (uint32_t)(dblk * 64 + q * 16) * 2);
                mma_f16(oacc[dblk * 8 + q * 2 + 0], Pf[kc], &vf[0]);
                mma_f16(oacc[dblk * 8 + q * 2 + 1], Pf[kc], &vf[2]);
            }
        }

        cb = (cb == 2) ? 0 : cb + 1;
        ib = (ib == 2) ? 0 : ib + 1;
    }

    // ---- epilogue ----
    lsum0 += __shfl_xor_sync(0xffffffffu, lsum0, 1);
    lsum0 += __shfl_xor_sync(0xffffffffu, lsum0, 2);
    lsum1 += __shfl_xor_sync(0xffffffffu, lsum1, 1);
    lsum1 += __shfl_xor_sync(0xffffffffu, lsum1, 2);
    const float inv0 = 1.0f / lsum0;
    const float inv1 = 1.0f / lsum1;

    const int r0 = q0 + 16 * w + (lane >> 2);
    const size_t base0 = ((size_t)b * SEQ + r0) * DIM + (lane & 3) * 2;
    const size_t base1 = base0 + (size_t)8 * DIM;
#pragma unroll
    for (int nto = 0; nto < 32; nto++) {
        float2 v0 = make_float2(oacc[nto][0] * inv0, oacc[nto][1] * inv0);
        float2 v1 = make_float2(oacc[nto][2] * inv1, oacc[nto][3] * inv1);
        *(float2*)&out[base0 + nto * 8] = v0;
        *(float2*)&out[base1 + nto * 8] = v1;
    }
}

// ---------------------------------------------------------------------------
extern "C" void kernel_launch(void* const* d_in, const int* in_sizes, int n_in,
                              void* d_out, int out_size)
{
    const float* x  = (const float*)d_in[0];
    const float* Wk = (const float*)d_in[1];
    const float* bk = (const float*)d_in[2];
    const float* Wq = (const float*)d_in[3];
    const float* bq = (const float*)d_in[4];
    const float* Wv = (const float*)d_in[5];
    const float* bv = (const float*)d_in[6];
    float* out = (float*)d_out;

    conv_w_kernel<<<dim3(64, 3), 256>>>(Wq, Wk, Wv);

    cudaFuncSetAttribute(proj_mma, cudaFuncAttributeMaxDynamicSharedMemorySize,
                         PROJ_SMEM);
    proj_mma<<<BATCH * SEQ / 128, 256, PROJ_SMEM>>>(x, bq, bk, bv);

    cudaFuncSetAttribute(attn_mma, cudaFuncAttributeMaxDynamicSharedMemorySize,
                         ATTN_SMEM);
    attn_mma<<<dim3(SEQ / 128, BATCH), 256, ATTN_SMEM>>>(out);
}